// round 1
// baseline (speedup 1.0000x reference)
#include <cuda_runtime.h>
#include <math.h>

// ---------------- Problem constants ----------------
#define NB     2
#define LQ     2048
#define DIM    320
#define HEADS  8
#define HD     40
#define NROWS  (NB * LQ)     // 4096
#define FFD    1280          // FF = 4*DIM ; wff1 -> 2*FFD cols

// ---------------- Scratch (static device memory; no allocs) ----------------
__device__ float g_ln  [NROWS * DIM];
__device__ float g_q   [NROWS * DIM];
__device__ float g_k   [NROWS * DIM];
__device__ float g_v   [NROWS * DIM];
__device__ float g_att [NROWS * DIM];
__device__ float g_res [NROWS * DIM];
__device__ float g_res2[NROWS * DIM];
__device__ float g_w2  [DIM * DIM];
__device__ float g_proj[NROWS * 2 * FFD];
__device__ float g_ffin[NROWS * FFD];

// ---------------- LayerNorm: one block per row, 320 threads ----------------
__global__ void ln_kernel(const float* __restrict__ x, const float* __restrict__ g,
                          const float* __restrict__ b, float* __restrict__ y) {
    __shared__ float red[32];
    int row = blockIdx.x;
    int tid = threadIdx.x;
    float v = x[row * DIM + tid];

    float s = v;
    #pragma unroll
    for (int o = 16; o > 0; o >>= 1) s += __shfl_xor_sync(0xffffffffu, s, o);
    if ((tid & 31) == 0) red[tid >> 5] = s;
    __syncthreads();
    if (tid < 32) {
        float t = (tid < (DIM / 32)) ? red[tid] : 0.0f;
        #pragma unroll
        for (int o = 16; o > 0; o >>= 1) t += __shfl_xor_sync(0xffffffffu, t, o);
        if (tid == 0) red[0] = t;
    }
    __syncthreads();
    float mean = red[0] * (1.0f / DIM);
    __syncthreads();

    float d = v - mean;
    float s2 = d * d;
    #pragma unroll
    for (int o = 16; o > 0; o >>= 1) s2 += __shfl_xor_sync(0xffffffffu, s2, o);
    if ((tid & 31) == 0) red[tid >> 5] = s2;
    __syncthreads();
    if (tid < 32) {
        float t = (tid < (DIM / 32)) ? red[tid] : 0.0f;
        #pragma unroll
        for (int o = 16; o > 0; o >>= 1) t += __shfl_xor_sync(0xffffffffu, t, o);
        if (tid == 0) red[0] = t;
    }
    __syncthreads();
    float var = red[0] * (1.0f / DIM);
    y[row * DIM + tid] = d * rsqrtf(var + 1e-5f) * g[tid] + b[tid];
}

// ---------------- Tiled SGEMM: C[M,N] = A[M,K] @ B[K,N] (+bias)(+res) ------
// 64x64 block tile, BK=16, 256 threads, 4x4 micro-tile per thread.
template<bool HAS_BIAS, bool HAS_RES>
__global__ void sgemm_kernel(const float* __restrict__ A, const float* __restrict__ B,
                             const float* __restrict__ bias, const float* __restrict__ res,
                             float* __restrict__ C, int M, int N, int K) {
    __shared__ float As[16][65];      // As[k][m], padded
    __shared__ float Bs[16][68];      // Bs[k][n], padded (float4-aligned stride)

    const int tid = threadIdx.x;
    const int tx = tid & 15;          // 0..15 -> n
    const int ty = tid >> 4;          // 0..15 -> m
    const int m0 = blockIdx.y * 64;
    const int n0 = blockIdx.x * 64;

    float acc[4][4];
    #pragma unroll
    for (int i = 0; i < 4; i++)
        #pragma unroll
        for (int j = 0; j < 4; j++) acc[i][j] = 0.0f;

    const int arow = tid >> 2;          // 0..63
    const int acol = (tid & 3) * 4;     // 0,4,8,12
    const int brow = tid >> 4;          // 0..15
    const int bcol = (tid & 15) * 4;    // 0..60

    for (int kt = 0; kt < K; kt += 16) {
        // load A tile [64 x 16] (K % 16 == 0 in all uses)
        {
            int gm = m0 + arow;
            float4 av = make_float4(0.f, 0.f, 0.f, 0.f);
            if (gm < M) av = *(const float4*)(A + (size_t)gm * K + kt + acol);
            As[acol + 0][arow] = av.x;
            As[acol + 1][arow] = av.y;
            As[acol + 2][arow] = av.z;
            As[acol + 3][arow] = av.w;
        }
        // load B tile [16 x 64]
        {
            int gn = n0 + bcol;
            float4 bv = make_float4(0.f, 0.f, 0.f, 0.f);
            if (gn < N) bv = *(const float4*)(B + (size_t)(kt + brow) * N + gn);
            *(float4*)&Bs[brow][bcol] = bv;
        }
        __syncthreads();

        #pragma unroll
        for (int k = 0; k < 16; k++) {
            float a0 = As[k][ty * 4 + 0];
            float a1 = As[k][ty * 4 + 1];
            float a2 = As[k][ty * 4 + 2];
            float a3 = As[k][ty * 4 + 3];
            float4 b4 = *(const float4*)&Bs[k][tx * 4];
            acc[0][0] += a0 * b4.x; acc[0][1] += a0 * b4.y; acc[0][2] += a0 * b4.z; acc[0][3] += a0 * b4.w;
            acc[1][0] += a1 * b4.x; acc[1][1] += a1 * b4.y; acc[1][2] += a1 * b4.z; acc[1][3] += a1 * b4.w;
            acc[2][0] += a2 * b4.x; acc[2][1] += a2 * b4.y; acc[2][2] += a2 * b4.z; acc[2][3] += a2 * b4.w;
            acc[3][0] += a3 * b4.x; acc[3][1] += a3 * b4.y; acc[3][2] += a3 * b4.z; acc[3][3] += a3 * b4.w;
        }
        __syncthreads();
    }

    #pragma unroll
    for (int i = 0; i < 4; i++) {
        int r = m0 + ty * 4 + i;
        if (r >= M) continue;
        #pragma unroll
        for (int j = 0; j < 4; j++) {
            int c = n0 + tx * 4 + j;
            if (c >= N) continue;
            float val = acc[i][j];
            if (HAS_BIAS) val += bias[c];
            if (HAS_RES)  val += res[(size_t)r * N + c];
            C[(size_t)r * N + c] = val;
        }
    }
}

// ---------------- Fused self-attention (flash-style, fp32) -----------------
// grid: (LQ/128, NB*HEADS), block: 128 threads, one q-row per thread.
__global__ void attn_kernel(const float* __restrict__ Q, const float* __restrict__ K,
                            const float* __restrict__ V, float* __restrict__ O) {
    const int bh = blockIdx.y;
    const int b = bh >> 3;
    const int h = bh & 7;
    const int q = blockIdx.x * 128 + threadIdx.x;
    const int rowbase = b * LQ;
    const float scale = rsqrtf((float)HD);

    __shared__ float Ks[64 * HD];
    __shared__ float Vs[64 * HD];

    float qreg[HD];
    const float4* qp = (const float4*)(Q + (size_t)(rowbase + q) * DIM + h * HD);
    #pragma unroll
    for (int i = 0; i < 10; i++) ((float4*)qreg)[i] = qp[i];

    float acc[HD];
    #pragma unroll
    for (int d = 0; d < HD; d++) acc[d] = 0.0f;
    float m = -1e30f, l = 0.0f;

    for (int kt = 0; kt < LQ; kt += 64) {
        // cooperative load of K/V tiles: 640 float4 each, 5 per thread
        #pragma unroll
        for (int j = 0; j < 5; j++) {
            int i4 = threadIdx.x + j * 128;   // 0..639
            int r  = i4 / 10;
            int c4 = i4 % 10;
            size_t goff = (size_t)(rowbase + kt + r) * DIM + h * HD;
            ((float4*)Ks)[i4] = *((const float4*)(K + goff) + c4);
            ((float4*)Vs)[i4] = *((const float4*)(V + goff) + c4);
        }
        __syncthreads();

        for (int j = 0; j < 64; j++) {
            const float4* kr = (const float4*)(Ks + j * HD);
            float s0 = 0.f, s1 = 0.f, s2 = 0.f, s3 = 0.f;
            #pragma unroll
            for (int d = 0; d < 10; d++) {
                float4 kv = kr[d];
                s0 += qreg[d * 4 + 0] * kv.x;
                s1 += qreg[d * 4 + 1] * kv.y;
                s2 += qreg[d * 4 + 2] * kv.z;
                s3 += qreg[d * 4 + 3] * kv.w;
            }
            float s = ((s0 + s1) + (s2 + s3)) * scale;
            if (s > m) {
                float corr = __expf(m - s);
                #pragma unroll
                for (int d = 0; d < HD; d++) acc[d] *= corr;
                l *= corr;
                m = s;
            }
            float p = __expf(s - m);
            l += p;
            const float4* vr = (const float4*)(Vs + j * HD);
            #pragma unroll
            for (int d = 0; d < 10; d++) {
                float4 vv = vr[d];
                acc[d * 4 + 0] += p * vv.x;
                acc[d * 4 + 1] += p * vv.y;
                acc[d * 4 + 2] += p * vv.z;
                acc[d * 4 + 3] += p * vv.w;
            }
        }
        __syncthreads();
    }

    float inv = 1.0f / l;
    float4* op = (float4*)(O + (size_t)(rowbase + q) * DIM + h * HD);
    #pragma unroll
    for (int i = 0; i < 10; i++) {
        op[i] = make_float4(acc[i * 4 + 0] * inv, acc[i * 4 + 1] * inv,
                            acc[i * 4 + 2] * inv, acc[i * 4 + 3] * inv);
    }
}

// ---------------- GEGLU: out = x * gelu_exact(gate) ------------------------
__global__ void geglu_kernel(const float* __restrict__ proj, float* __restrict__ out) {
    int idx = blockIdx.x * blockDim.x + threadIdx.x;
    if (idx >= NROWS * FFD) return;
    int r = idx / FFD;
    int c = idx - r * FFD;
    float x  = proj[(size_t)r * (2 * FFD) + c];
    float gt = proj[(size_t)r * (2 * FFD) + FFD + c];
    float ge = 0.5f * gt * (1.0f + erff(gt * 0.7071067811865476f));
    out[idx] = x * ge;
}

// ---------------- Launch ----------------------------------------------------
extern "C" void kernel_launch(void* const* d_in, const int* in_sizes, int n_in,
                              void* d_out, int out_size) {
    (void)in_sizes; (void)n_in; (void)out_size;
    const float* hidden = (const float*)d_in[0];
    // d_in[1] encoder_hidden_states: dead (softmax row-sums are exactly 1)
    const float* ln1_g = (const float*)d_in[2];
    const float* ln1_b = (const float*)d_in[3];
    const float* wq1   = (const float*)d_in[4];
    const float* wk1   = (const float*)d_in[5];
    const float* wv1   = (const float*)d_in[6];
    const float* wo1   = (const float*)d_in[7];
    const float* bo1   = (const float*)d_in[8];
    const float* ln2_g = (const float*)d_in[9];
    const float* ln2_b = (const float*)d_in[10];
    // d_in[11]=wq2, d_in[12]=wk2: dead
    const float* wvh   = (const float*)d_in[13];
    const float* wo2   = (const float*)d_in[14];
    const float* bo2   = (const float*)d_in[15];
    const float* ln3_g = (const float*)d_in[16];
    const float* ln3_b = (const float*)d_in[17];
    const float* wff1  = (const float*)d_in[18];
    const float* bff1  = (const float*)d_in[19];
    const float* wff2  = (const float*)d_in[20];
    const float* bff2  = (const float*)d_in[21];
    float* out = (float*)d_out;

    float *s_ln, *s_q, *s_k, *s_v, *s_att, *s_res, *s_res2, *s_w2, *s_proj, *s_ffin;
    cudaGetSymbolAddress((void**)&s_ln,   g_ln);
    cudaGetSymbolAddress((void**)&s_q,    g_q);
    cudaGetSymbolAddress((void**)&s_k,    g_k);
    cudaGetSymbolAddress((void**)&s_v,    g_v);
    cudaGetSymbolAddress((void**)&s_att,  g_att);
    cudaGetSymbolAddress((void**)&s_res,  g_res);
    cudaGetSymbolAddress((void**)&s_res2, g_res2);
    cudaGetSymbolAddress((void**)&s_w2,   g_w2);
    cudaGetSymbolAddress((void**)&s_proj, g_proj);
    cudaGetSymbolAddress((void**)&s_ffin, g_ffin);

    auto grid = [](int M, int N) { return dim3((N + 63) / 64, (M + 63) / 64); };

    // ---- block 1: LN1 + self-attention + wo1 + residual ----
    ln_kernel<<<NROWS, DIM>>>(hidden, ln1_g, ln1_b, s_ln);
    sgemm_kernel<false, false><<<grid(NROWS, DIM), 256>>>(s_ln, wq1, nullptr, nullptr, s_q, NROWS, DIM, DIM);
    sgemm_kernel<false, false><<<grid(NROWS, DIM), 256>>>(s_ln, wk1, nullptr, nullptr, s_k, NROWS, DIM, DIM);
    sgemm_kernel<false, false><<<grid(NROWS, DIM), 256>>>(s_ln, wv1, nullptr, nullptr, s_v, NROWS, DIM, DIM);
    attn_kernel<<<dim3(LQ / 128, NB * HEADS), 128>>>(s_q, s_k, s_v, s_att);
    sgemm_kernel<true, true><<<grid(NROWS, DIM), 256>>>(s_att, wo1, bo1, hidden, s_res, NROWS, DIM, DIM);

    // ---- block 2: LN2 + (cross-attn == h @ (wvh@wo2) + bo2) + residual ----
    ln_kernel<<<NROWS, DIM>>>(s_res, ln2_g, ln2_b, s_ln);
    sgemm_kernel<false, false><<<grid(DIM, DIM), 256>>>(wvh, wo2, nullptr, nullptr, s_w2, DIM, DIM, DIM);
    sgemm_kernel<true, true><<<grid(NROWS, DIM), 256>>>(s_ln, s_w2, bo2, s_res, s_res2, NROWS, DIM, DIM);

    // ---- block 3: LN3 + GEGLU FF + residual ----
    ln_kernel<<<NROWS, DIM>>>(s_res2, ln3_g, ln3_b, s_ln);
    sgemm_kernel<true, false><<<grid(NROWS, 2 * FFD), 256>>>(s_ln, wff1, bff1, nullptr, s_proj, NROWS, 2 * FFD, DIM);
    geglu_kernel<<<(NROWS * FFD + 255) / 256, 256>>>(s_proj, s_ffin);
    sgemm_kernel<true, true><<<grid(NROWS, DIM), 256>>>(s_ffin, wff2, bff2, s_res2, out, NROWS, DIM, FFD);
}

// round 3
// speedup vs baseline: 2.3082x; 2.3082x over previous
#include <cuda_runtime.h>
#include <cuda_bf16.h>
#include <math.h>
#include <stdint.h>

// ---------------- Problem constants ----------------
#define NB     2
#define LQ     2048
#define DIM    320
#define NH     8
#define HD     40
#define HDP    64                // padded head dim for MMA
#define BH     (NB * NH)         // 16
#define NROWS  (NB * LQ)         // 4096
#define FFD    1280
#define QKVN   960               // fused q|k|v output width

typedef __nv_bfloat16 bf16;

// ---------------- Static scratch ----------------
__device__ bf16  g_lnb [NROWS * DIM];
__device__ bf16  g_qkv [NROWS * QKVN];
__device__ bf16  g_qp  [(size_t)BH * LQ * HDP];
__device__ bf16  g_kp  [(size_t)BH * LQ * HDP];
__device__ bf16  g_vt  [(size_t)BH * HDP * LQ];
__device__ bf16  g_P   [(size_t)BH * LQ * LQ];      // 134 MB
__device__ float g_rowsum[BH * LQ];
__device__ float g_onum[(size_t)BH * LQ * HDP];
__device__ bf16  g_attn[NROWS * DIM];
__device__ float g_res [NROWS * DIM];
__device__ float g_res2[NROWS * DIM];
__device__ bf16  g_proj[(size_t)NROWS * 2 * FFD];
__device__ bf16  g_ffin[(size_t)NROWS * FFD];
// transposed bf16 weights [N,K]
__device__ bf16  g_wqkvt[QKVN * DIM];
__device__ bf16  g_wo1t [DIM * DIM];
__device__ bf16  g_w2t  [DIM * DIM];
__device__ bf16  g_wff1t[2 * FFD * DIM];
__device__ bf16  g_wff2t[DIM * FFD];

// ---------------- Helpers ----------------
__device__ __forceinline__ uint32_t s2u(const void* p) {
    uint32_t a;
    asm("{ .reg .u64 t; cvta.to.shared.u64 t, %1; cvt.u32.u64 %0, t; }" : "=r"(a) : "l"(p));
    return a;
}
__device__ __forceinline__ void cpa16(uint32_t s, const void* g) {
    asm volatile("cp.async.cg.shared.global [%0], [%1], 16;\n" :: "r"(s), "l"(g));
}
__device__ __forceinline__ void cpa_commit() { asm volatile("cp.async.commit_group;\n" ::: "memory"); }
template<int N> __device__ __forceinline__ void cpa_wait() {
    asm volatile("cp.async.wait_group %0;\n" :: "n"(N) : "memory");
}
__device__ __forceinline__ void mma16816(float* d, const uint32_t* a, const uint32_t* b) {
    asm volatile("mma.sync.aligned.m16n8k16.row.col.f32.bf16.bf16.f32 "
        "{%0,%1,%2,%3}, {%4,%5,%6,%7}, {%8,%9}, {%0,%1,%2,%3};"
        : "+f"(d[0]), "+f"(d[1]), "+f"(d[2]), "+f"(d[3])
        : "r"(a[0]), "r"(a[1]), "r"(a[2]), "r"(a[3]), "r"(b[0]), "r"(b[1]));
}
// fast exp: FMA-only (avoids MUFU bottleneck); rel err ~4e-5
__device__ __forceinline__ float fexp(float x) {
    float y = x * 1.44269504f;
    float z = y + 12582912.0f;                 // round-to-nearest integer trick
    int   ni = __float_as_int(z) - 0x4B400000; // integer part
    float f = y - (z - 12582912.0f);           // fractional part in [-0.5, 0.5]
    float p = 0.00961812910f;
    p = fmaf(p, f, 0.0555041087f);
    p = fmaf(p, f, 0.240226507f);
    p = fmaf(p, f, 0.693147182f);
    p = fmaf(p, f, 1.0f);
    return __int_as_float(__float_as_int(p) + (ni << 23));
}

// ---------------- GEMM: C[M,N] = A[M,K] @ B[N,K]^T (bf16 in, fp32 accum) ------
// 128x128 tile, BK=32, 256 threads (8 warps, each 64x32), double-buffered cp.async.
#define ASTRIDE 40   // smem row stride in elements (conflict-free: 80B = 20 words mod 32)

struct GP {
    const bf16* A; long long sAz; int lda;
    const bf16* B; long long sBz; int ldb, nB;
    float* Cf; bf16* Cb; long long sCz; int ldc;
    const float* bias; const float* res; float* rowsum;
    int M, N, K; float scale;
};

// EPI: 0 = fp32 out (+bias?)(+res?), 1 = bf16 out (+bias?), 2 = exp->bf16 + rowsum
template<int EPI>
__global__ void __launch_bounds__(256) gemm_k(GP p) {
    __shared__ bf16 sA[2][128 * ASTRIDE];
    __shared__ bf16 sB[2][128 * ASTRIDE];

    const int tid = threadIdx.x;
    const int wid = tid >> 5, lane = tid & 31;
    const int g = lane >> 2, t = lane & 3;
    const int wm = (wid >> 2) * 64, wn = (wid & 3) * 32;
    const int n0 = blockIdx.x * 128, m0 = blockIdx.y * 128;

    const bf16* A = p.A + (long long)blockIdx.z * p.sAz;
    const bf16* B = p.B + (long long)blockIdx.z * p.sBz;

    float acc[4][4][4];
    #pragma unroll
    for (int i = 0; i < 4; i++)
        #pragma unroll
        for (int j = 0; j < 4; j++)
            #pragma unroll
            for (int q = 0; q < 4; q++) acc[i][j][q] = 0.0f;

    auto load_stage = [&](int ch, int st) {
        const int k0 = ch * 32;
        #pragma unroll
        for (int j = 0; j < 2; j++) {
            int id = tid + j * 256;           // 0..511
            int r = id >> 2, c = id & 3;      // row 0..127, 16B chunk 0..3
            cpa16(s2u(&sA[st][r * ASTRIDE + c * 8]),
                  A + (size_t)(m0 + r) * p.lda + k0 + c * 8);
            int rn = n0 + r; if (rn >= p.nB) rn = p.nB - 1;
            cpa16(s2u(&sB[st][r * ASTRIDE + c * 8]),
                  B + (size_t)rn * p.ldb + k0 + c * 8);
        }
        cpa_commit();
    };

    auto compute_stage = [&](int st) {
        #pragma unroll
        for (int ks = 0; ks < 2; ks++) {
            const int kb = ks * 16 + 2 * t;
            uint32_t af[4][4], bfr[4][2];
            #pragma unroll
            for (int mt = 0; mt < 4; mt++) {
                const bf16* pa = &sA[st][(wm + mt * 16 + g) * ASTRIDE + kb];
                af[mt][0] = *(const uint32_t*)pa;
                af[mt][1] = *(const uint32_t*)(pa + 8 * ASTRIDE);
                af[mt][2] = *(const uint32_t*)(pa + 8);
                af[mt][3] = *(const uint32_t*)(pa + 8 * ASTRIDE + 8);
            }
            #pragma unroll
            for (int nt = 0; nt < 4; nt++) {
                const bf16* pb = &sB[st][(wn + nt * 8 + g) * ASTRIDE + kb];
                bfr[nt][0] = *(const uint32_t*)pb;
                bfr[nt][1] = *(const uint32_t*)(pb + 8);
            }
            #pragma unroll
            for (int mt = 0; mt < 4; mt++)
                #pragma unroll
                for (int nt = 0; nt < 4; nt++)
                    mma16816(acc[mt][nt], af[mt], bfr[nt]);
        }
    };

    const int NC = p.K >> 5;
    load_stage(0, 0);
    for (int i = 0; i < NC; i++) {
        if (i + 1 < NC) { load_stage(i + 1, (i + 1) & 1); cpa_wait<1>(); }
        else            { cpa_wait<0>(); }
        __syncthreads();
        compute_stage(i & 1);
        __syncthreads();
    }

    // ---- epilogue ----
    float* Cf = p.Cf ? p.Cf + (long long)blockIdx.z * p.sCz : nullptr;
    bf16*  Cb = p.Cb ? p.Cb + (long long)blockIdx.z * p.sCz : nullptr;

    #pragma unroll
    for (int mt = 0; mt < 4; mt++) {
        const int r0 = m0 + wm + mt * 16 + g;
        const int r1 = r0 + 8;
        float rs0 = 0.0f, rs1 = 0.0f;
        #pragma unroll
        for (int nt = 0; nt < 4; nt++) {
            const int cb = n0 + wn + nt * 8;
            if (cb >= p.N) continue;
            const int c = cb + 2 * t;
            float v0 = acc[mt][nt][0], v1 = acc[mt][nt][1];
            float v2 = acc[mt][nt][2], v3 = acc[mt][nt][3];
            if (EPI == 2) {
                float e0 = fexp(v0 * p.scale), e1 = fexp(v1 * p.scale);
                float e2 = fexp(v2 * p.scale), e3 = fexp(v3 * p.scale);
                rs0 += e0 + e1; rs1 += e2 + e3;
                __nv_bfloat162 h0 = __floats2bfloat162_rn(e0, e1);
                __nv_bfloat162 h1 = __floats2bfloat162_rn(e2, e3);
                *(uint32_t*)(Cb + (size_t)r0 * p.ldc + c) = *(uint32_t*)&h0;
                *(uint32_t*)(Cb + (size_t)r1 * p.ldc + c) = *(uint32_t*)&h1;
            } else if (EPI == 1) {
                if (p.bias) {
                    float2 bb = *(const float2*)(p.bias + c);
                    v0 += bb.x; v1 += bb.y; v2 += bb.x; v3 += bb.y;
                }
                __nv_bfloat162 h0 = __floats2bfloat162_rn(v0, v1);
                __nv_bfloat162 h1 = __floats2bfloat162_rn(v2, v3);
                *(uint32_t*)(Cb + (size_t)r0 * p.ldc + c) = *(uint32_t*)&h0;
                *(uint32_t*)(Cb + (size_t)r1 * p.ldc + c) = *(uint32_t*)&h1;
            } else {
                if (p.bias) {
                    float2 bb = *(const float2*)(p.bias + c);
                    v0 += bb.x; v1 += bb.y; v2 += bb.x; v3 += bb.y;
                }
                if (p.res) {
                    float2 q0 = *(const float2*)(p.res + (size_t)r0 * p.ldc + c);
                    float2 q1 = *(const float2*)(p.res + (size_t)r1 * p.ldc + c);
                    v0 += q0.x; v1 += q0.y; v2 += q1.x; v3 += q1.y;
                }
                *(float2*)(Cf + (size_t)r0 * p.ldc + c) = make_float2(v0, v1);
                *(float2*)(Cf + (size_t)r1 * p.ldc + c) = make_float2(v2, v3);
            }
        }
        if (EPI == 2) {
            rs0 += __shfl_xor_sync(0xffffffffu, rs0, 1);
            rs0 += __shfl_xor_sync(0xffffffffu, rs0, 2);
            rs1 += __shfl_xor_sync(0xffffffffu, rs1, 1);
            rs1 += __shfl_xor_sync(0xffffffffu, rs1, 2);
            if (t == 0) {
                atomicAdd(p.rowsum + (size_t)blockIdx.z * p.M + r0, rs0);
                atomicAdd(p.rowsum + (size_t)blockIdx.z * p.M + r1, rs1);
            }
        }
    }
}

// ---------------- LayerNorm (fp32 in -> bf16 out) ----------------
__global__ void ln_k(const float* __restrict__ x, const float* __restrict__ g,
                     const float* __restrict__ b, bf16* __restrict__ y) {
    __shared__ float red[32];
    int row = blockIdx.x, tid = threadIdx.x;
    float v = x[row * DIM + tid];
    float s = v;
    #pragma unroll
    for (int o = 16; o > 0; o >>= 1) s += __shfl_xor_sync(0xffffffffu, s, o);
    if ((tid & 31) == 0) red[tid >> 5] = s;
    __syncthreads();
    if (tid < 32) {
        float t2 = (tid < (DIM / 32)) ? red[tid] : 0.0f;
        #pragma unroll
        for (int o = 16; o > 0; o >>= 1) t2 += __shfl_xor_sync(0xffffffffu, t2, o);
        if (tid == 0) red[0] = t2;
    }
    __syncthreads();
    float mean = red[0] * (1.0f / DIM);
    __syncthreads();
    float d = v - mean;
    float s2 = d * d;
    #pragma unroll
    for (int o = 16; o > 0; o >>= 1) s2 += __shfl_xor_sync(0xffffffffu, s2, o);
    if ((tid & 31) == 0) red[tid >> 5] = s2;
    __syncthreads();
    if (tid < 32) {
        float t2 = (tid < (DIM / 32)) ? red[tid] : 0.0f;
        #pragma unroll
        for (int o = 16; o > 0; o >>= 1) t2 += __shfl_xor_sync(0xffffffffu, t2, o);
        if (tid == 0) red[0] = t2;
    }
    __syncthreads();
    float var = red[0] * (1.0f / DIM);
    y[row * DIM + tid] = __float2bfloat16(d * rsqrtf(var + 1e-5f) * g[tid] + b[tid]);
}

// ---------------- Weight transpose: W[K,N] fp32 -> Wt[N,K] bf16 ----------------
__global__ void transw_k(const float* __restrict__ W, bf16* __restrict__ Wt, int K, int N) {
    int idx = blockIdx.x * 256 + threadIdx.x;
    if (idx >= K * N) return;
    int n = idx / K, k = idx - n * K;
    Wt[idx] = __float2bfloat16(W[(size_t)k * N + n]);
}

// ---------------- Fold: w2t[n,k] = sum_j wvh[k,j] * wo2[j,n] ------------------
__global__ void fold_k(const float* __restrict__ wvh, const float* __restrict__ wo2,
                       bf16* __restrict__ w2t) {
    int idx = blockIdx.x * 256 + threadIdx.x;
    if (idx >= DIM * DIM) return;
    int n = idx % DIM, k = idx / DIM;
    float s = 0.0f;
    for (int j = 0; j < DIM; j++) s += wvh[k * DIM + j] * wo2[j * DIM + n];
    w2t[n * DIM + k] = __float2bfloat16(s);
}

// ---------------- Pack q/k into padded per-head layout [BH,LQ,HDP] ------------
__global__ void pack_k(const bf16* __restrict__ qkv, bf16* __restrict__ qp, bf16* __restrict__ kp) {
    int idx = blockIdx.x * 256 + threadIdx.x;
    if (idx >= BH * LQ * HDP) return;
    int dd = idx & 63, tt = idx >> 6;
    int q = tt & (LQ - 1), z = tt >> 11;
    int b = z >> 3, h = z & 7;
    bf16 zero = __float2bfloat16(0.0f);
    size_t src = (size_t)(b * LQ + q) * QKVN + h * HD + dd;
    bool ok = dd < HD;
    qp[idx] = ok ? qkv[src] : zero;
    kp[idx] = ok ? qkv[src + DIM] : zero;
}

// ---------------- Transpose v per head: vt[BH,HDP,LQ] -------------------------
__global__ void vt_k(const bf16* __restrict__ qkv, bf16* __restrict__ vt) {
    int idx = blockIdx.x * 256 + threadIdx.x;
    if (idx >= BH * HDP * LQ) return;
    int kk = idx & (LQ - 1), tt = idx >> 11;
    int dd = tt & 63, z = tt >> 6;
    int b = z >> 3, h = z & 7;
    bf16 zero = __float2bfloat16(0.0f);
    vt[idx] = (dd < HD) ? qkv[(size_t)(b * LQ + kk) * QKVN + 2 * DIM + h * HD + dd] : zero;
}

// ---------------- Divide by rowsum, unpack heads -> attn bf16 -----------------
__global__ void div_k(const float* __restrict__ onum, const float* __restrict__ rowsum,
                      bf16* __restrict__ attn) {
    int idx = blockIdx.x * 256 + threadIdx.x;
    if (idx >= BH * LQ * HD) return;
    int dd = idx % HD, tt = idx / HD;
    int q = tt & (LQ - 1), z = tt >> 11;
    int b = z >> 3, h = z & 7;
    float v = onum[((size_t)z * LQ + q) * HDP + dd] / rowsum[z * LQ + q];
    attn[(size_t)(b * LQ + q) * DIM + h * HD + dd] = __float2bfloat16(v);
}

// ---------------- GEGLU (bf16 in/out) -----------------------------------------
__global__ void geglu_k(const bf16* __restrict__ proj, bf16* __restrict__ out) {
    int idx = blockIdx.x * 256 + threadIdx.x;
    if (idx >= NROWS * FFD) return;
    int r = idx / FFD, c = idx - r * FFD;
    float x  = __bfloat162float(proj[(size_t)r * (2 * FFD) + c]);
    float gt = __bfloat162float(proj[(size_t)r * (2 * FFD) + FFD + c]);
    float ge = 0.5f * gt * (1.0f + erff(gt * 0.7071067811865476f));
    out[idx] = __float2bfloat16(x * ge);
}

// ---------------- Launch ----------------
extern "C" void kernel_launch(void* const* d_in, const int* in_sizes, int n_in,
                              void* d_out, int out_size) {
    (void)in_sizes; (void)n_in; (void)out_size;
    const float* hidden = (const float*)d_in[0];
    const float* ln1_g = (const float*)d_in[2];
    const float* ln1_b = (const float*)d_in[3];
    const float* wq1   = (const float*)d_in[4];
    const float* wk1   = (const float*)d_in[5];
    const float* wv1   = (const float*)d_in[6];
    const float* wo1   = (const float*)d_in[7];
    const float* bo1   = (const float*)d_in[8];
    const float* ln2_g = (const float*)d_in[9];
    const float* ln2_b = (const float*)d_in[10];
    const float* wvh   = (const float*)d_in[13];
    const float* wo2   = (const float*)d_in[14];
    const float* bo2   = (const float*)d_in[15];
    const float* ln3_g = (const float*)d_in[16];
    const float* ln3_b = (const float*)d_in[17];
    const float* wff1  = (const float*)d_in[18];
    const float* bff1  = (const float*)d_in[19];
    const float* wff2  = (const float*)d_in[20];
    const float* bff2  = (const float*)d_in[21];
    float* out = (float*)d_out;

    bf16 *s_lnb, *s_qkv, *s_qp, *s_kp, *s_vt, *s_P, *s_attn, *s_proj, *s_ffin;
    bf16 *s_wqkvt, *s_wo1t, *s_w2t, *s_wff1t, *s_wff2t;
    float *s_rowsum, *s_onum, *s_res, *s_res2;
    cudaGetSymbolAddress((void**)&s_lnb, g_lnb);
    cudaGetSymbolAddress((void**)&s_qkv, g_qkv);
    cudaGetSymbolAddress((void**)&s_qp, g_qp);
    cudaGetSymbolAddress((void**)&s_kp, g_kp);
    cudaGetSymbolAddress((void**)&s_vt, g_vt);
    cudaGetSymbolAddress((void**)&s_P, g_P);
    cudaGetSymbolAddress((void**)&s_rowsum, g_rowsum);
    cudaGetSymbolAddress((void**)&s_onum, g_onum);
    cudaGetSymbolAddress((void**)&s_attn, g_attn);
    cudaGetSymbolAddress((void**)&s_res, g_res);
    cudaGetSymbolAddress((void**)&s_res2, g_res2);
    cudaGetSymbolAddress((void**)&s_proj, g_proj);
    cudaGetSymbolAddress((void**)&s_ffin, g_ffin);
    cudaGetSymbolAddress((void**)&s_wqkvt, g_wqkvt);
    cudaGetSymbolAddress((void**)&s_wo1t, g_wo1t);
    cudaGetSymbolAddress((void**)&s_w2t, g_w2t);
    cudaGetSymbolAddress((void**)&s_wff1t, g_wff1t);
    cudaGetSymbolAddress((void**)&s_wff2t, g_wff2t);

    const float scale = 0.15811388300841897f;   // 1/sqrt(40)

    // ---- weight prep ----
    transw_k<<<(DIM * DIM + 255) / 256, 256>>>(wq1, s_wqkvt, DIM, DIM);
    transw_k<<<(DIM * DIM + 255) / 256, 256>>>(wk1, s_wqkvt + DIM * DIM, DIM, DIM);
    transw_k<<<(DIM * DIM + 255) / 256, 256>>>(wv1, s_wqkvt + 2 * DIM * DIM, DIM, DIM);
    transw_k<<<(DIM * DIM + 255) / 256, 256>>>(wo1, s_wo1t, DIM, DIM);
    transw_k<<<(DIM * 2 * FFD + 255) / 256, 256>>>(wff1, s_wff1t, DIM, 2 * FFD);
    transw_k<<<(FFD * DIM + 255) / 256, 256>>>(wff2, s_wff2t, FFD, DIM);
    fold_k<<<(DIM * DIM + 255) / 256, 256>>>(wvh, wo2, s_w2t);

    GP p{};

    // ---- LN1 + fused QKV GEMM ----
    ln_k<<<NROWS, DIM>>>(hidden, ln1_g, ln1_b, s_lnb);
    p = GP{ s_lnb, 0, DIM,  s_wqkvt, 0, DIM, QKVN,
            nullptr, s_qkv, 0, QKVN,  nullptr, nullptr, nullptr,
            NROWS, QKVN, DIM, 1.0f };
    gemm_k<1><<<dim3(8, 32, 1), 256>>>(p);

    // ---- attention prep ----
    pack_k<<<(BH * LQ * HDP + 255) / 256, 256>>>(s_qkv, s_qp, s_kp);
    vt_k<<<(BH * HDP * LQ + 255) / 256, 256>>>(s_qkv, s_vt);
    cudaMemsetAsync(s_rowsum, 0, BH * LQ * sizeof(float));

    // ---- P = exp(Q K^T * scale), rowsum ----
    p = GP{ s_qp, (long long)LQ * HDP, HDP,
            s_kp, (long long)LQ * HDP, HDP, LQ,
            nullptr, s_P, (long long)LQ * LQ, LQ,
            nullptr, nullptr, s_rowsum,
            LQ, LQ, HDP, scale };
    gemm_k<2><<<dim3(16, 16, BH), 256>>>(p);

    // ---- O_num = P @ V ----
    p = GP{ s_P, (long long)LQ * LQ, LQ,
            s_vt, (long long)HDP * LQ, LQ, HDP,
            s_onum, nullptr, (long long)LQ * HDP, HDP,
            nullptr, nullptr, nullptr,
            LQ, HDP, LQ, 1.0f };
    gemm_k<0><<<dim3(1, 16, BH), 256>>>(p);

    div_k<<<(BH * LQ * HD + 255) / 256, 256>>>(s_onum, s_rowsum, s_attn);

    // ---- wo1 + bias + residual(hidden) ----
    p = GP{ s_attn, 0, DIM,  s_wo1t, 0, DIM, DIM,
            s_res, nullptr, 0, DIM,  bo1, hidden, nullptr,
            NROWS, DIM, DIM, 1.0f };
    gemm_k<0><<<dim3(3, 32, 1), 256>>>(p);

    // ---- block 2: LN2 + folded cross-attn + residual ----
    ln_k<<<NROWS, DIM>>>(s_res, ln2_g, ln2_b, s_lnb);
    p = GP{ s_lnb, 0, DIM,  s_w2t, 0, DIM, DIM,
            s_res2, nullptr, 0, DIM,  bo2, s_res, nullptr,
            NROWS, DIM, DIM, 1.0f };
    gemm_k<0><<<dim3(3, 32, 1), 256>>>(p);

    // ---- block 3: LN3 + GEGLU FF + residual ----
    ln_k<<<NROWS, DIM>>>(s_res2, ln3_g, ln3_b, s_lnb);
    p = GP{ s_lnb, 0, DIM,  s_wff1t, 0, DIM, 2 * FFD,
            nullptr, s_proj, 0, 2 * FFD,  bff1, nullptr, nullptr,
            NROWS, 2 * FFD, DIM, 1.0f };
    gemm_k<1><<<dim3(20, 32, 1), 256>>>(p);
    geglu_k<<<(NROWS * FFD + 255) / 256, 256>>>(s_proj, s_ffin);
    p = GP{ s_ffin, 0, FFD,  s_wff2t, 0, FFD, DIM,
            out, nullptr, 0, DIM,  bff2, s_res2, nullptr,
            NROWS, DIM, FFD, 1.0f };
    gemm_k<0><<<dim3(3, 32, 1), 256>>>(p);
}

// round 4
// speedup vs baseline: 3.9504x; 1.7114x over previous
#include <cuda_runtime.h>
#include <cuda_bf16.h>
#include <math.h>
#include <stdint.h>

// ---------------- Problem constants ----------------
#define NB     2
#define LQ     2048
#define DIM    320
#define NH     8
#define HD     40
#define HDP    64
#define BH     (NB * NH)         // 16
#define NROWS  (NB * LQ)         // 4096
#define FFD    1280
#define QKVN   960

typedef __nv_bfloat16 bf16;

// ---------------- Static scratch ----------------
__device__ bf16  g_lnb [NROWS * DIM];
__device__ bf16  g_qkv [NROWS * QKVN];
__device__ bf16  g_vt  [(size_t)BH * HDP * LQ];
__device__ bf16  g_attn[NROWS * DIM];
__device__ float g_res [NROWS * DIM];
__device__ float g_res2[NROWS * DIM];
__device__ bf16  g_ffin[(size_t)NROWS * FFD];
__device__ bf16  g_wqkvt[QKVN * DIM];
__device__ bf16  g_wo1t [DIM * DIM];
__device__ bf16  g_w2t  [DIM * DIM];
__device__ bf16  g_wff1t[2 * FFD * DIM];   // interleaved: col 2j=x_j, 2j+1=gate_j
__device__ bf16  g_wff2t[DIM * FFD];
__device__ float g_bffi [2 * FFD];         // interleaved bias

// ---------------- Helpers ----------------
__device__ __forceinline__ uint32_t s2u(const void* p) {
    uint32_t a;
    asm("{ .reg .u64 t; cvta.to.shared.u64 t, %1; cvt.u32.u64 %0, t; }" : "=r"(a) : "l"(p));
    return a;
}
__device__ __forceinline__ void cpa16(uint32_t s, const void* g) {
    asm volatile("cp.async.cg.shared.global [%0], [%1], 16;\n" :: "r"(s), "l"(g));
}
__device__ __forceinline__ void cpa16z(uint32_t s, const void* g, int nb) {
    asm volatile("cp.async.cg.shared.global [%0], [%1], 16, %2;\n" :: "r"(s), "l"(g), "r"(nb));
}
__device__ __forceinline__ void cpa_commit() { asm volatile("cp.async.commit_group;\n" ::: "memory"); }
template<int N> __device__ __forceinline__ void cpa_wait() {
    asm volatile("cp.async.wait_group %0;\n" :: "n"(N) : "memory");
}
__device__ __forceinline__ void mma16816(float* d, const uint32_t* a, const uint32_t* b) {
    asm volatile("mma.sync.aligned.m16n8k16.row.col.f32.bf16.bf16.f32 "
        "{%0,%1,%2,%3}, {%4,%5,%6,%7}, {%8,%9}, {%0,%1,%2,%3};"
        : "+f"(d[0]), "+f"(d[1]), "+f"(d[2]), "+f"(d[3])
        : "r"(a[0]), "r"(a[1]), "r"(a[2]), "r"(a[3]), "r"(b[0]), "r"(b[1]));
}
__device__ __forceinline__ float fexp(float x) {
    float y = x * 1.44269504f;
    float z = y + 12582912.0f;
    int   ni = __float_as_int(z) - 0x4B400000;
    float f = y - (z - 12582912.0f);
    float p = 0.00961812910f;
    p = fmaf(p, f, 0.0555041087f);
    p = fmaf(p, f, 0.240226507f);
    p = fmaf(p, f, 0.693147182f);
    p = fmaf(p, f, 1.0f);
    return __int_as_float(__float_as_int(p) + (ni << 23));
}
__device__ __forceinline__ uint32_t packbf2(float a, float b) {
    __nv_bfloat162 h = __floats2bfloat162_rn(a, b);
    return *(uint32_t*)&h;
}

// ---------------- GEMM: C[M,N] = A[M,K] @ B[N,K]^T ----------------
#define ASTRIDE 40

struct GP {
    const bf16* A; int lda;
    const bf16* B; int ldb, nB;
    float* Cf; bf16* Cb; int ldc;
    const float* bias; const float* res;
    int M, N, K;
};

// EPI: 0 = fp32 out (+bias?)(+res?), 1 = bf16 out, 3 = fused GEGLU (interleaved)
template<int EPI>
__global__ void __launch_bounds__(256) gemm_k(GP p) {
    __shared__ bf16 sA[2][128 * ASTRIDE];
    __shared__ bf16 sB[2][128 * ASTRIDE];

    const int tid = threadIdx.x;
    const int wid = tid >> 5, lane = tid & 31;
    const int g = lane >> 2, t = lane & 3;
    const int wm = (wid >> 2) * 64, wn = (wid & 3) * 32;
    const int n0 = blockIdx.x * 128, m0 = blockIdx.y * 128;

    float acc[4][4][4];
    #pragma unroll
    for (int i = 0; i < 4; i++)
        #pragma unroll
        for (int j = 0; j < 4; j++)
            #pragma unroll
            for (int q = 0; q < 4; q++) acc[i][j][q] = 0.0f;

    auto load_stage = [&](int ch, int st) {
        const int k0 = ch * 32;
        #pragma unroll
        for (int j = 0; j < 2; j++) {
            int id = tid + j * 256;
            int r = id >> 2, c = id & 3;
            cpa16(s2u(&sA[st][r * ASTRIDE + c * 8]),
                  p.A + (size_t)(m0 + r) * p.lda + k0 + c * 8);
            int rn = n0 + r; if (rn >= p.nB) rn = p.nB - 1;
            cpa16(s2u(&sB[st][r * ASTRIDE + c * 8]),
                  p.B + (size_t)rn * p.ldb + k0 + c * 8);
        }
        cpa_commit();
    };

    auto compute_stage = [&](int st) {
        #pragma unroll
        for (int ks = 0; ks < 2; ks++) {
            const int kb = ks * 16 + 2 * t;
            uint32_t af[4][4], bfr[4][2];
            #pragma unroll
            for (int mt = 0; mt < 4; mt++) {
                const bf16* pa = &sA[st][(wm + mt * 16 + g) * ASTRIDE + kb];
                af[mt][0] = *(const uint32_t*)pa;
                af[mt][1] = *(const uint32_t*)(pa + 8 * ASTRIDE);
                af[mt][2] = *(const uint32_t*)(pa + 8);
                af[mt][3] = *(const uint32_t*)(pa + 8 * ASTRIDE + 8);
            }
            #pragma unroll
            for (int nt = 0; nt < 4; nt++) {
                const bf16* pb = &sB[st][(wn + nt * 8 + g) * ASTRIDE + kb];
                bfr[nt][0] = *(const uint32_t*)pb;
                bfr[nt][1] = *(const uint32_t*)(pb + 8);
            }
            #pragma unroll
            for (int mt = 0; mt < 4; mt++)
                #pragma unroll
                for (int nt = 0; nt < 4; nt++)
                    mma16816(acc[mt][nt], af[mt], bfr[nt]);
        }
    };

    const int NC = p.K >> 5;
    load_stage(0, 0);
    for (int i = 0; i < NC; i++) {
        if (i + 1 < NC) { load_stage(i + 1, (i + 1) & 1); cpa_wait<1>(); }
        else            { cpa_wait<0>(); }
        __syncthreads();
        compute_stage(i & 1);
        __syncthreads();
    }

    #pragma unroll
    for (int mt = 0; mt < 4; mt++) {
        const int r0 = m0 + wm + mt * 16 + g;
        const int r1 = r0 + 8;
        #pragma unroll
        for (int nt = 0; nt < 4; nt++) {
            const int cb = n0 + wn + nt * 8;
            if (cb >= p.N) continue;
            const int c = cb + 2 * t;
            float v0 = acc[mt][nt][0], v1 = acc[mt][nt][1];
            float v2 = acc[mt][nt][2], v3 = acc[mt][nt][3];
            if (EPI == 3) {
                v0 += p.bias[c]; v1 += p.bias[c + 1];
                v2 += p.bias[c]; v3 += p.bias[c + 1];
                float o0 = v0 * 0.5f * v1 * (1.0f + erff(v1 * 0.7071067811865476f));
                float o1 = v2 * 0.5f * v3 * (1.0f + erff(v3 * 0.7071067811865476f));
                int j = c >> 1;
                p.Cb[(size_t)r0 * p.ldc + j] = __float2bfloat16(o0);
                p.Cb[(size_t)r1 * p.ldc + j] = __float2bfloat16(o1);
            } else if (EPI == 1) {
                *(uint32_t*)(p.Cb + (size_t)r0 * p.ldc + c) = packbf2(v0, v1);
                *(uint32_t*)(p.Cb + (size_t)r1 * p.ldc + c) = packbf2(v2, v3);
            } else {
                if (p.bias) {
                    float2 bb = *(const float2*)(p.bias + c);
                    v0 += bb.x; v1 += bb.y; v2 += bb.x; v3 += bb.y;
                }
                if (p.res) {
                    float2 q0 = *(const float2*)(p.res + (size_t)r0 * p.ldc + c);
                    float2 q1 = *(const float2*)(p.res + (size_t)r1 * p.ldc + c);
                    v0 += q0.x; v1 += q0.y; v2 += q1.x; v3 += q1.y;
                }
                *(float2*)(p.Cf + (size_t)r0 * p.ldc + c) = make_float2(v0, v1);
                *(float2*)(p.Cf + (size_t)r1 * p.ldc + c) = make_float2(v2, v3);
            }
        }
    }
}

// ---------------- Fused flash attention ----------------
// grid (LQ/128, BH), 256 threads. Warp-tile: 16 q-rows x 128 k-cols.
#define KSTR 56
#define VSTR 136
#define FL_SMEM (2 * 128 * KSTR * 2 + 2 * 64 * VSTR * 2)   // 63488 B

__global__ void __launch_bounds__(256) flash_k(const bf16* __restrict__ qkv,
                                               const bf16* __restrict__ vt,
                                               bf16* __restrict__ attn) {
    extern __shared__ bf16 fsm[];
    bf16* sK = fsm;                     // [2][128*KSTR]
    bf16* sV = fsm + 2 * 128 * KSTR;    // [2][64*VSTR]

    const int tid = threadIdx.x, wid = tid >> 5, lane = tid & 31;
    const int g = lane >> 2, t = lane & 3;
    const int z = blockIdx.y, b = z >> 3, h = z & 7;
    const int m0 = blockIdx.x * 128;
    const float scale = 0.15811388300841897f;   // 1/sqrt(40)

    // Q fragments in registers (d = 0..47; cols 40..47 zeroed)
    uint32_t qf[3][4];
    {
        const bf16* qb = qkv + (size_t)(b * LQ + m0 + wid * 16) * QKVN + h * HD;
        #pragma unroll
        for (int ks = 0; ks < 3; ks++) {
            int c0 = ks * 16 + 2 * t;
            qf[ks][0] = *(const uint32_t*)(qb + (size_t)g * QKVN + c0);
            qf[ks][1] = *(const uint32_t*)(qb + (size_t)(g + 8) * QKVN + c0);
            if (ks < 2) {
                qf[ks][2] = *(const uint32_t*)(qb + (size_t)g * QKVN + c0 + 8);
                qf[ks][3] = *(const uint32_t*)(qb + (size_t)(g + 8) * QKVN + c0 + 8);
            } else { qf[ks][2] = 0u; qf[ks][3] = 0u; }
        }
    }

    auto loadKV = [&](int kt, int st) {
        #pragma unroll
        for (int j = 0; j < 3; j++) {          // K: 128 rows x 6 chunks (40 bf16 + zfill)
            int id = tid + j * 256;
            int r = id / 6, c = id % 6;
            uint32_t so = s2u(sK + st * 128 * KSTR + r * KSTR + c * 8);
            const bf16* gp = qkv + (size_t)(b * LQ + kt * 128 + r) * QKVN + DIM + h * HD + c * 8;
            cpa16z(so, gp, c < 5 ? 16 : 0);
        }
        #pragma unroll
        for (int j = 0; j < 4; j++) {          // V^T: 64 rows x 16 chunks
            int id = tid + j * 256;
            int r = id >> 4, c = id & 15;
            uint32_t so = s2u(sV + st * 64 * VSTR + r * VSTR + c * 8);
            cpa16(so, vt + ((size_t)z * HDP + r) * LQ + kt * 128 + c * 8);
        }
        cpa_commit();
    };

    float accO[8][4];
    #pragma unroll
    for (int i = 0; i < 8; i++)
        #pragma unroll
        for (int q = 0; q < 4; q++) accO[i][q] = 0.0f;
    float l0 = 0.0f, l1 = 0.0f;

    loadKV(0, 0);
    for (int kt = 0; kt < LQ / 128; kt++) {
        const int st = kt & 1;
        if (kt + 1 < LQ / 128) { loadKV(kt + 1, st ^ 1); cpa_wait<1>(); }
        else                   { cpa_wait<0>(); }
        __syncthreads();

        // ---- S = Q @ K^T ----
        float accS[16][4];
        #pragma unroll
        for (int i = 0; i < 16; i++)
            #pragma unroll
            for (int q = 0; q < 4; q++) accS[i][q] = 0.0f;

        const bf16* kb = sK + st * 128 * KSTR;
        #pragma unroll
        for (int ks = 0; ks < 3; ks++) {
            const int kc = ks * 16 + 2 * t;
            #pragma unroll
            for (int nt = 0; nt < 16; nt++) {
                const bf16* pb = kb + (nt * 8 + g) * KSTR + kc;
                uint32_t bfr[2] = { *(const uint32_t*)pb, *(const uint32_t*)(pb + 8) };
                mma16816(accS[nt], qf[ks], bfr);
            }
        }

        // ---- P = exp(S*scale), pack to A-frags, accumulate rowsum ----
        uint32_t pf[8][4];
        #pragma unroll
        for (int ks2 = 0; ks2 < 8; ks2++) {
            float e0 = fexp(accS[2 * ks2][0] * scale), e1 = fexp(accS[2 * ks2][1] * scale);
            float e2 = fexp(accS[2 * ks2][2] * scale), e3 = fexp(accS[2 * ks2][3] * scale);
            float f0 = fexp(accS[2 * ks2 + 1][0] * scale), f1 = fexp(accS[2 * ks2 + 1][1] * scale);
            float f2 = fexp(accS[2 * ks2 + 1][2] * scale), f3 = fexp(accS[2 * ks2 + 1][3] * scale);
            l0 += (e0 + e1) + (f0 + f1);
            l1 += (e2 + e3) + (f2 + f3);
            pf[ks2][0] = packbf2(e0, e1);
            pf[ks2][1] = packbf2(e2, e3);
            pf[ks2][2] = packbf2(f0, f1);
            pf[ks2][3] = packbf2(f2, f3);
        }

        // ---- O += P @ V ----
        const bf16* vb = sV + st * 64 * VSTR;
        #pragma unroll
        for (int ks2 = 0; ks2 < 8; ks2++) {
            const int kc = ks2 * 16 + 2 * t;
            #pragma unroll
            for (int nt = 0; nt < 8; nt++) {
                const bf16* pb = vb + (nt * 8 + g) * VSTR + kc;
                uint32_t bfr[2] = { *(const uint32_t*)pb, *(const uint32_t*)(pb + 8) };
                mma16816(accO[nt], pf[ks2], bfr);
            }
        }
        __syncthreads();
    }

    // ---- normalize + write ----
    l0 += __shfl_xor_sync(0xffffffffu, l0, 1);
    l0 += __shfl_xor_sync(0xffffffffu, l0, 2);
    l1 += __shfl_xor_sync(0xffffffffu, l1, 1);
    l1 += __shfl_xor_sync(0xffffffffu, l1, 2);
    const float i0 = 1.0f / l0, i1 = 1.0f / l1;
    const int r0 = b * LQ + m0 + wid * 16 + g, r1 = r0 + 8;
    #pragma unroll
    for (int nt = 0; nt < 5; nt++) {            // only d < 40
        int col = h * HD + nt * 8 + 2 * t;
        *(uint32_t*)(attn + (size_t)r0 * DIM + col) = packbf2(accO[nt][0] * i0, accO[nt][1] * i0);
        *(uint32_t*)(attn + (size_t)r1 * DIM + col) = packbf2(accO[nt][2] * i1, accO[nt][3] * i1);
    }
}

// ---------------- LayerNorm (fp32 in -> bf16 out) ----------------
__global__ void ln_k(const float* __restrict__ x, const float* __restrict__ g,
                     const float* __restrict__ b, bf16* __restrict__ y) {
    __shared__ float red[32];
    int row = blockIdx.x, tid = threadIdx.x;
    float v = x[row * DIM + tid];
    float s = v;
    #pragma unroll
    for (int o = 16; o > 0; o >>= 1) s += __shfl_xor_sync(0xffffffffu, s, o);
    if ((tid & 31) == 0) red[tid >> 5] = s;
    __syncthreads();
    if (tid < 32) {
        float t2 = (tid < (DIM / 32)) ? red[tid] : 0.0f;
        #pragma unroll
        for (int o = 16; o > 0; o >>= 1) t2 += __shfl_xor_sync(0xffffffffu, t2, o);
        if (tid == 0) red[0] = t2;
    }
    __syncthreads();
    float mean = red[0] * (1.0f / DIM);
    __syncthreads();
    float d = v - mean;
    float s2 = d * d;
    #pragma unroll
    for (int o = 16; o > 0; o >>= 1) s2 += __shfl_xor_sync(0xffffffffu, s2, o);
    if ((tid & 31) == 0) red[tid >> 5] = s2;
    __syncthreads();
    if (tid < 32) {
        float t2 = (tid < (DIM / 32)) ? red[tid] : 0.0f;
        #pragma unroll
        for (int o = 16; o > 0; o >>= 1) t2 += __shfl_xor_sync(0xffffffffu, t2, o);
        if (tid == 0) red[0] = t2;
    }
    __syncthreads();
    float var = red[0] * (1.0f / DIM);
    y[row * DIM + tid] = __float2bfloat16(d * rsqrtf(var + 1e-5f) * g[tid] + b[tid]);
}

// ---------------- Merged prep: all weight transposes + fold + bias ----------
// segments: [0,102400) fold | wq | wk | wv | wo1 | [512000,921600) wff2
//           [921600,1740800) wff1 interleaved | [1740800,1743360) bias
__global__ void prep_k(const float* __restrict__ wq1, const float* __restrict__ wk1,
                       const float* __restrict__ wv1, const float* __restrict__ wo1,
                       const float* __restrict__ wvh, const float* __restrict__ wo2,
                       const float* __restrict__ wff1, const float* __restrict__ wff2,
                       const float* __restrict__ bff1) {
    int idx = blockIdx.x * 256 + threadIdx.x;
    if (idx < 102400) {
        int n = idx % 320, k = idx / 320;
        float s = 0.0f;
        for (int j = 0; j < 320; j++) s += wvh[k * 320 + j] * wo2[j * 320 + n];
        g_w2t[n * 320 + k] = __float2bfloat16(s);
    } else if (idx < 204800) {
        int i = idx - 102400; int n = i / 320, k = i % 320;
        g_wqkvt[i] = __float2bfloat16(wq1[k * 320 + n]);
    } else if (idx < 307200) {
        int i = idx - 204800; int n = i / 320, k = i % 320;
        g_wqkvt[102400 + i] = __float2bfloat16(wk1[k * 320 + n]);
    } else if (idx < 409600) {
        int i = idx - 307200; int n = i / 320, k = i % 320;
        g_wqkvt[204800 + i] = __float2bfloat16(wv1[k * 320 + n]);
    } else if (idx < 512000) {
        int i = idx - 409600; int n = i / 320, k = i % 320;
        g_wo1t[i] = __float2bfloat16(wo1[k * 320 + n]);
    } else if (idx < 921600) {
        int i = idx - 512000; int n = i / 1280, k = i % 1280;
        g_wff2t[i] = __float2bfloat16(wff2[k * 320 + n]);
    } else if (idx < 1740800) {
        int i = idx - 921600; int c = i / 320, k = i % 320;
        int j = (c >> 1) + (c & 1) * FFD;
        g_wff1t[i] = __float2bfloat16(wff1[(size_t)k * 2 * FFD + j]);
    } else if (idx < 1743360) {
        int c = idx - 1740800;
        g_bffi[c] = bff1[(c >> 1) + (c & 1) * FFD];
    }
}

// ---------------- V transpose (smem tiled): qkv -> vt[BH][HDP][LQ] ----------
__global__ void vt2_k(const bf16* __restrict__ qkv, bf16* __restrict__ vt) {
    __shared__ bf16 st[64][41];
    const int z = blockIdx.y, b = z >> 3, h = z & 7;
    const int k0 = blockIdx.x * 64;
    const int tid = threadIdx.x;
    for (int id = tid; id < 64 * HD; id += 256) {
        int r = id / HD, d = id - r * HD;
        st[r][d] = qkv[(size_t)(b * LQ + k0 + r) * QKVN + 2 * DIM + h * HD + d];
    }
    __syncthreads();
    bf16 zero = __float2bfloat16(0.0f);
    #pragma unroll
    for (int j = 0; j < 16; j++) {
        int oid = tid + j * 256;               // 0..4095
        int d = oid >> 6, kk = oid & 63;
        vt[((size_t)z * HDP + d) * LQ + k0 + kk] = (d < HD) ? st[kk][d] : zero;
    }
}

// ---------------- Launch ----------------
extern "C" void kernel_launch(void* const* d_in, const int* in_sizes, int n_in,
                              void* d_out, int out_size) {
    (void)in_sizes; (void)n_in; (void)out_size;
    const float* hidden = (const float*)d_in[0];
    const float* ln1_g = (const float*)d_in[2];
    const float* ln1_b = (const float*)d_in[3];
    const float* wq1   = (const float*)d_in[4];
    const float* wk1   = (const float*)d_in[5];
    const float* wv1   = (const float*)d_in[6];
    const float* wo1   = (const float*)d_in[7];
    const float* bo1   = (const float*)d_in[8];
    const float* ln2_g = (const float*)d_in[9];
    const float* ln2_b = (const float*)d_in[10];
    const float* wvh   = (const float*)d_in[13];
    const float* wo2   = (const float*)d_in[14];
    const float* bo2   = (const float*)d_in[15];
    const float* ln3_g = (const float*)d_in[16];
    const float* ln3_b = (const float*)d_in[17];
    const float* wff1  = (const float*)d_in[18];
    const float* bff1  = (const float*)d_in[19];
    const float* wff2  = (const float*)d_in[20];
    const float* bff2  = (const float*)d_in[21];
    float* out = (float*)d_out;

    bf16 *s_lnb, *s_qkv, *s_vt, *s_attn, *s_ffin;
    bf16 *s_wqkvt, *s_wo1t, *s_w2t, *s_wff1t, *s_wff2t;
    float *s_res, *s_res2, *s_bffi;
    cudaGetSymbolAddress((void**)&s_lnb, g_lnb);
    cudaGetSymbolAddress((void**)&s_qkv, g_qkv);
    cudaGetSymbolAddress((void**)&s_vt, g_vt);
    cudaGetSymbolAddress((void**)&s_attn, g_attn);
    cudaGetSymbolAddress((void**)&s_res, g_res);
    cudaGetSymbolAddress((void**)&s_res2, g_res2);
    cudaGetSymbolAddress((void**)&s_ffin, g_ffin);
    cudaGetSymbolAddress((void**)&s_wqkvt, g_wqkvt);
    cudaGetSymbolAddress((void**)&s_wo1t, g_wo1t);
    cudaGetSymbolAddress((void**)&s_w2t, g_w2t);
    cudaGetSymbolAddress((void**)&s_wff1t, g_wff1t);
    cudaGetSymbolAddress((void**)&s_wff2t, g_wff2t);
    cudaGetSymbolAddress((void**)&s_bffi, g_bffi);

    cudaFuncSetAttribute(flash_k, cudaFuncAttributeMaxDynamicSharedMemorySize, FL_SMEM);

    GP p{};

    // 1. all weight prep in one kernel
    prep_k<<<(1743360 + 255) / 256, 256>>>(wq1, wk1, wv1, wo1, wvh, wo2, wff1, wff2, bff1);

    // 2. LN1 + fused QKV GEMM
    ln_k<<<NROWS, DIM>>>(hidden, ln1_g, ln1_b, s_lnb);
    p = GP{ s_lnb, DIM,  s_wqkvt, DIM, QKVN,
            nullptr, s_qkv, QKVN,  nullptr, nullptr, NROWS, QKVN, DIM };
    gemm_k<1><<<dim3(8, 32), 256>>>(p);

    // 3. V transpose + fused flash attention
    vt2_k<<<dim3(LQ / 64, BH), 256>>>(s_qkv, s_vt);
    flash_k<<<dim3(LQ / 128, BH), 256, FL_SMEM>>>(s_qkv, s_vt, s_attn);

    // 4. wo1 + bias + residual
    p = GP{ s_attn, DIM,  s_wo1t, DIM, DIM,
            s_res, nullptr, DIM,  bo1, hidden, NROWS, DIM, DIM };
    gemm_k<0><<<dim3(3, 32), 256>>>(p);

    // 5. LN2 + folded cross-attn + residual
    ln_k<<<NROWS, DIM>>>(s_res, ln2_g, ln2_b, s_lnb);
    p = GP{ s_lnb, DIM,  s_w2t, DIM, DIM,
            s_res2, nullptr, DIM,  bo2, s_res, NROWS, DIM, DIM };
    gemm_k<0><<<dim3(3, 32), 256>>>(p);

    // 6. LN3 + FF1 (fused GEGLU) + FF2 + residual
    ln_k<<<NROWS, DIM>>>(s_res2, ln3_g, ln3_b, s_lnb);
    p = GP{ s_lnb, DIM,  s_wff1t, DIM, 2 * FFD,
            nullptr, s_ffin, FFD,  s_bffi, nullptr, NROWS, 2 * FFD, DIM };
    gemm_k<3><<<dim3(20, 32), 256>>>(p);
    p = GP{ s_ffin, FFD,  s_wff2t, FFD, DIM,
            out, nullptr, DIM,  bff2, s_res2, NROWS, DIM, FFD };
    gemm_k<0><<<dim3(3, 32), 256>>>(p);
}